// round 15
// baseline (speedup 1.0000x reference)
#include <cuda_runtime.h>
#include <stdint.h>

// BNB 8-bit embedding dequant gather (harness materializes int8 q_weight as int32):
//   out[token,:] = (float)q_weight[x[token],:] * (absmax[x[token]] / 127)
// x[32768] i32, q_weight[50257,1024] i32, absmax[50257] f32, out[32768,1024] f32.
//
// CONVERGED FINAL (best dur 41.44us; kernel 35.8-36.7us band @ DRAM ~66%):
//   - 4 tokens/CTA, 256 threads, one int4 (16B) gather lane per thread
//   - 4 independent gathers in flight per thread (MLP=4) before any consume
//   - no barriers; index loads are CTA-wide broadcasts
//   - __stcs output stores (evict-first; beats __stwt by ~1us of replay wall
//     time — write-through drains to DRAM at the kernel/replay boundary)
// Falsified levers (clean A/Bs): MLP>4, persistent pipelining, evict_last
// (both encodings), 32B policy lanes, write-through. The kernel sits at the
// mixed random-read + streaming-write DRAM ceiling (~5.3TB/s, ~193MB/replay:
// 134MB irreducible writes + ~59MB steady-state table reads).

static constexpr int DIM = 1024;
static constexpr int THREADS = 256;        // DIM/4 int4 lanes
static constexpr int TOKENS_PER_CTA = 4;

__global__ __launch_bounds__(THREADS, 8)
void bnb8_embed_kernel(const int* __restrict__ x,
                       const int* __restrict__ qw,
                       const float* __restrict__ absmax,
                       float* __restrict__ out,
                       int n_tokens)
{
    const int base = blockIdx.x * TOKENS_PER_CTA;

    // Broadcast index loads (same addr across CTA -> 1 request + broadcast).
    int rows[TOKENS_PER_CTA];
#pragma unroll
    for (int i = 0; i < TOKENS_PER_CTA; i++)
        rows[i] = __ldg(x + base + i);

    float scales[TOKENS_PER_CTA];
#pragma unroll
    for (int i = 0; i < TOKENS_PER_CTA; i++)
        scales[i] = __ldg(absmax + rows[i]) * (1.0f / 127.0f);

    // 4 independent 16B gathers in flight before any consumption.
    int4 v[TOKENS_PER_CTA];
#pragma unroll
    for (int i = 0; i < TOKENS_PER_CTA; i++) {
        const int4* rp = reinterpret_cast<const int4*>(qw + (long long)rows[i] * DIM);
        v[i] = __ldg(rp + threadIdx.x);
    }

#pragma unroll
    for (int i = 0; i < TOKENS_PER_CTA; i++) {
        float4 o;
        o.x = (float)v[i].x * scales[i];
        o.y = (float)v[i].y * scales[i];
        o.z = (float)v[i].z * scales[i];
        o.w = (float)v[i].w * scales[i];
        float4* op = reinterpret_cast<float4*>(out + (long long)(base + i) * DIM);
        __stcs(op + threadIdx.x, o);   // evict-first: output never re-read
    }
}

extern "C" void kernel_launch(void* const* d_in, const int* in_sizes, int n_in,
                              void* d_out, int out_size)
{
    // Bind by element count: qw largest, x smallest, absmax the remaining one.
    long long max_sz = -1;
    int qw_idx = -1;
    for (int i = 0; i < n_in; i++)
        if ((long long)in_sizes[i] > max_sz) { max_sz = in_sizes[i]; qw_idx = i; }

    long long min_sz = 0x7fffffffffffLL;
    int x_idx = -1;
    for (int i = 0; i < n_in; i++) {
        if (i == qw_idx) continue;
        if ((long long)in_sizes[i] < min_sz) { min_sz = in_sizes[i]; x_idx = i; }
    }
    int am_idx = -1;
    for (int i = 0; i < n_in; i++)
        if (i != qw_idx && i != x_idx) am_idx = i;

    const int*   x      = (const int*)d_in[x_idx];
    const int*   qw     = (const int*)d_in[qw_idx];
    const float* absmax = (const float*)d_in[am_idx];
    float*       out    = (float*)d_out;
    const int n_tokens  = in_sizes[x_idx];  // 32768

    const int grid = (n_tokens + TOKENS_PER_CTA - 1) / TOKENS_PER_CTA;
    bnb8_embed_kernel<<<grid, THREADS>>>(x, qw, absmax, out, n_tokens);
}

// round 16
// speedup vs baseline: 1.0069x; 1.0069x over previous
#include <cuda_runtime.h>
#include <stdint.h>

// BNB 8-bit embedding dequant gather (harness materializes int8 q_weight as int32):
//   out[token,:] = (float)q_weight[x[token],:] * (absmax[x[token]] / 127)
// x[32768] i32, q_weight[50257,1024] i32, absmax[50257] f32, out[32768,1024] f32.
//
// CONVERGED FINAL (best dur 41.44us; kernel 35.8-36.7us band @ DRAM ~66%):
//   - 4 tokens/CTA, 256 threads, one int4 (16B) gather lane per thread
//   - 4 independent gathers in flight per thread (MLP=4) before any consume
//   - no barriers; index loads are CTA-wide broadcasts
//   - __stcs output stores (evict-first; beats __stwt by ~1us of replay wall
//     time — write-through pays its DRAM drain at the replay boundary)
// Falsified levers (clean A/Bs over 14 rounds): MLP>4 (reg-capped or
// occupancy-priced; occ x MLP invariant), persistent pipelining (+ALU,
// -locality), evict_last policies (both PTX encodings; policy LDG path
// slower), 32B policy lanes (occupancy collapse), write-through stores.
// Ledger: 134MB irreducible writes + ~59MB steady-state reads (96MB
// first-touch minus ~37MB cross-replay L2 retention) at ~5.3TB/s mixed-stream
// DRAM throughput = ~36us kernel. This is the floor for this access pattern.

static constexpr int DIM = 1024;
static constexpr int THREADS = 256;        // DIM/4 int4 lanes
static constexpr int TOKENS_PER_CTA = 4;

__global__ __launch_bounds__(THREADS, 8)
void bnb8_embed_kernel(const int* __restrict__ x,
                       const int* __restrict__ qw,
                       const float* __restrict__ absmax,
                       float* __restrict__ out,
                       int n_tokens)
{
    const int base = blockIdx.x * TOKENS_PER_CTA;

    // Broadcast index loads (same addr across CTA -> 1 request + broadcast).
    int rows[TOKENS_PER_CTA];
#pragma unroll
    for (int i = 0; i < TOKENS_PER_CTA; i++)
        rows[i] = __ldg(x + base + i);

    float scales[TOKENS_PER_CTA];
#pragma unroll
    for (int i = 0; i < TOKENS_PER_CTA; i++)
        scales[i] = __ldg(absmax + rows[i]) * (1.0f / 127.0f);

    // 4 independent 16B gathers in flight before any consumption.
    int4 v[TOKENS_PER_CTA];
#pragma unroll
    for (int i = 0; i < TOKENS_PER_CTA; i++) {
        const int4* rp = reinterpret_cast<const int4*>(qw + (long long)rows[i] * DIM);
        v[i] = __ldg(rp + threadIdx.x);
    }

#pragma unroll
    for (int i = 0; i < TOKENS_PER_CTA; i++) {
        float4 o;
        o.x = (float)v[i].x * scales[i];
        o.y = (float)v[i].y * scales[i];
        o.z = (float)v[i].z * scales[i];
        o.w = (float)v[i].w * scales[i];
        float4* op = reinterpret_cast<float4*>(out + (long long)(base + i) * DIM);
        __stcs(op + threadIdx.x, o);   // evict-first: output never re-read
    }
}

extern "C" void kernel_launch(void* const* d_in, const int* in_sizes, int n_in,
                              void* d_out, int out_size)
{
    // Bind by element count: qw largest, x smallest, absmax the remaining one.
    long long max_sz = -1;
    int qw_idx = -1;
    for (int i = 0; i < n_in; i++)
        if ((long long)in_sizes[i] > max_sz) { max_sz = in_sizes[i]; qw_idx = i; }

    long long min_sz = 0x7fffffffffffLL;
    int x_idx = -1;
    for (int i = 0; i < n_in; i++) {
        if (i == qw_idx) continue;
        if ((long long)in_sizes[i] < min_sz) { min_sz = in_sizes[i]; x_idx = i; }
    }
    int am_idx = -1;
    for (int i = 0; i < n_in; i++)
        if (i != qw_idx && i != x_idx) am_idx = i;

    const int*   x      = (const int*)d_in[x_idx];
    const int*   qw     = (const int*)d_in[qw_idx];
    const float* absmax = (const float*)d_in[am_idx];
    float*       out    = (float*)d_out;
    const int n_tokens  = in_sizes[x_idx];  // 32768

    const int grid = (n_tokens + TOKENS_PER_CTA - 1) / TOKENS_PER_CTA;
    bnb8_embed_kernel<<<grid, THREADS>>>(x, qw, absmax, out, n_tokens);
}